// round 5
// baseline (speedup 1.0000x reference)
#include <cuda_runtime.h>

#define WSZ 21
#define KW  43
#define IH  128
#define IW  128
#define IB  2
#define NPIX (IB*IH*IW)   // 32768
#define NREG 64
#define CAP  262144
#define SCREEN_T (-26.0f)

// scratch (__device__ globals: no allocation allowed)
__device__ float4 g_s4[NPIX];    // smooth channels, .w = |s|^2
__device__ float4 g_o4[NPIX];    // orig channels,   .w = |o|^2
__device__ float  g_mask[NPIX];  // m_large
__device__ float4 g_tmp4[NPIX];  // conv scratch
__device__ float  g_swtab[KW+1]; // [KW] = total 2D spatial weight
__device__ double g_partial[256];
__device__ unsigned g_cnt[NREG*32];     // padded counters (one per 128B line)
__device__ unsigned g_list[NREG*CAP];   // survivor ids

__device__ __forceinline__ float ex2f(float x) {
    float y;
    asm("ex2.approx.ftz.f32 %0, %1;" : "=f"(y) : "f"(x));
    return y;
}
__device__ __forceinline__ float lg2f(float x) {
    float y;
    asm("lg2.approx.ftz.f32 %0, %1;" : "=f"(y) : "f"(x));
    return y;
}

__device__ __forceinline__ int refl(int p, int n) {
    if (p < 0) p = -p;
    if (p >= n) p = 2*n - 2 - p;
    return p;
}

// Pack channels into float4 (+|.|^2 in .w), Sobel masks, spatial table, zero counters.
__global__ void prep_kernel(const float* __restrict__ orig, const float* __restrict__ smo) {
    int idx = blockIdx.x * blockDim.x + threadIdx.x;
    if (idx < 256) g_partial[idx] = 0.0;
    if (idx < NREG) g_cnt[idx*32] = 0u;
    if (idx < KW) {
        float d = (float)(idx - WSZ);
        g_swtab[idx] = expf(-(1.0f/98.0f) * d * d);   // SIGMA_SPACE = 1/(2*49)
    }
    if (idx == KW) {
        float s1 = 0.f;
        for (int x = -WSZ; x <= WSZ; ++x) s1 += expf(-(1.0f/98.0f) * (float)(x*x));
        g_swtab[KW] = s1 * s1;
    }
    if (idx >= NPIX) return;
    int c = idx & (IW-1);
    int r = (idx >> 7) & (IH-1);
    int b = idx >> 14;
    const float* ob = orig + b*3*IH*IW;
    const float* sb = smo  + b*3*IH*IW;
    int rm = refl(r-1, IH), rp = refl(r+1, IH);
    int cm = refl(c-1, IW), cp = refl(c+1, IW);
    float eo = 0.f, es = 0.f;
    float oo[3], ss[3];
    #pragma unroll
    for (int ch = 0; ch < 3; ++ch) {
        const float* p = ob + ch*IH*IW;
        float a00=p[rm*IW+cm], a01=p[rm*IW+c], a02=p[rm*IW+cp];
        float a10=p[r *IW+cm], a11=p[r *IW+c], a12=p[r *IW+cp];
        float a20=p[rp*IW+cm], a21=p[rp*IW+c], a22=p[rp*IW+cp];
        float gx = (a02 + 2.f*a12 + a22) - (a00 + 2.f*a10 + a20);
        float gy = (a20 + 2.f*a21 + a22) - (a00 + 2.f*a01 + a02);
        eo += sqrtf(gx*gx + gy*gy);
        oo[ch] = a11;
        const float* q = sb + ch*IH*IW;
        float b00=q[rm*IW+cm], b01=q[rm*IW+c], b02=q[rm*IW+cp];
        float b10=q[r *IW+cm], b11=q[r *IW+c], b12=q[r *IW+cp];
        float b20=q[rp*IW+cm], b21=q[rp*IW+c], b22=q[rp*IW+cp];
        float hx = (b02 + 2.f*b12 + b22) - (b00 + 2.f*b10 + b20);
        float hy = (b20 + 2.f*b21 + b22) - (b00 + 2.f*b01 + b02);
        es += sqrtf(hx*hx + hy*hy);
        ss[ch] = b11;
    }
    g_mask[idx] = ((eo < 20.f) && (es - eo > 10.f)) ? 1.f : 0.f;
    g_s4[idx] = make_float4(ss[0], ss[1], ss[2], ss[0]*ss[0]+ss[1]*ss[1]+ss[2]*ss[2]);
    g_o4[idx] = make_float4(oo[0], oo[1], oo[2], oo[0]*oo[0]+oo[1]*oo[1]+oo[2]*oo[2]);
}

// Pass 1 of separable Gaussian conv over (s.x,s.y,s.z,|s|^2): along columns.
__global__ void __launch_bounds__(128) conv_y_kernel() {
    __shared__ float4 row[IW + 2*WSZ];
    __shared__ float  wy[KW];
    int t  = threadIdx.x;
    int rg = blockIdx.x;          // 0..255 = batch*row
    int b  = rg >> 7;
    int r  = rg & (IH-1);
    int base = b*IH*IW + r*IW;
    for (int j = t; j < IW + 2*WSZ; j += 128)
        row[j] = g_s4[base + refl(j - WSZ, IW)];
    if (t < KW) wy[t] = g_swtab[t];
    __syncthreads();
    float4 a = make_float4(0.f, 0.f, 0.f, 0.f);
    #pragma unroll 4
    for (int j = 0; j < KW; ++j) {
        float  w = wy[j];
        float4 v = row[t + j];
        a.x = fmaf(w, v.x, a.x);
        a.y = fmaf(w, v.y, a.y);
        a.z = fmaf(w, v.z, a.z);
        a.w = fmaf(w, v.w, a.w);
    }
    g_tmp4[base + t] = a;
}

// Pass 2 (rows) + m_large term reduce:
//   large_i = mL_i * ( W*|s_i|^2 + (G*|s|^2)_i - 2 s_i . (G*s)_i )
__global__ void __launch_bounds__(256) large_kernel() {
    __shared__ float wpart[8];
    int t   = threadIdx.x;
    int idx = blockIdx.x * 256 + t;
    int c = idx & (IW-1);
    int r = (idx >> 7) & (IH-1);
    int b = idx >> 14;
    float4 a = make_float4(0.f, 0.f, 0.f, 0.f);
    #pragma unroll 4
    for (int j = 0; j < KW; ++j) {
        int rr = refl(r + j - WSZ, IH);
        float  w = g_swtab[j];
        float4 v = g_tmp4[b*IH*IW + rr*IW + c];
        a.x = fmaf(w, v.x, a.x);
        a.y = fmaf(w, v.y, a.y);
        a.z = fmaf(w, v.z, a.z);
        a.w = fmaf(w, v.w, a.w);
    }
    float4 s  = g_s4[idx];
    float Wsum = g_swtab[KW];
    float dot = s.x*a.x + s.y*a.y + s.z*a.z;
    float val = g_mask[idx] * (fmaf(Wsum, s.w, a.w) - 2.f*dot);
    #pragma unroll
    for (int off = 16; off; off >>= 1)
        val += __shfl_xor_sync(0xffffffffu, val, off);
    if ((t & 31) == 0) wpart[t >> 5] = val;
    __syncthreads();
    if (t == 0) {
        float bs = 0.f;
        #pragma unroll
        for (int w = 0; w < 8; ++w) bs += wpart[w];
        atomicAdd(&g_partial[blockIdx.x & 255], (double)bs);
    }
}

// Screen: find units with non-negligible wr = exp(-50|do|^2), compact their ids.
// One block per (batch*row, x-offset). 128 threads = one per column.
__global__ void __launch_bounds__(128) screen_kernel() {
    __shared__ float4 sO[IW + 2*WSZ];   // 170

    int t  = threadIdx.x;
    int bx = blockIdx.x;
    int xob = bx % KW;           // 0..42
    int rg = bx / KW;            // 0..255
    int b  = rg >> 7;
    int r  = rg & (IH-1);

    int srow = refl(r + xob - WSZ, IH);
    int base = b*IH*IW + srow*IW;
    for (int j = t; j < IW + 2*WSZ; j += 128)
        sO[j] = g_o4[base + refl(j - WSZ, IW)];
    __syncthreads();

    int cidx = b*IH*IW + r*IW + t;
    float4 oc = g_o4[cidx];
    bool msnz = (g_mask[cidx] == 0.f);     // m_small != 0
    float c0 = -72.13475204444817f * oc.w;
    unsigned idbase = ((unsigned)cidx << 11) | (unsigned)(xob * KW);
    int reg = bx & (NREG - 1);
    unsigned* cnt = &g_cnt[reg * 32];
    unsigned* lst = &g_list[reg * CAP];
    int lane = t & 31;
    unsigned lanemask = (lane == 31) ? 0x7fffffffu : ((1u << lane) - 1u);

    #pragma unroll 1
    for (int j = 0; j < KW; ++j) {
        float4 o = sO[t + j];
        float dot = fmaf(oc.z, o.z, fmaf(oc.y, o.y, oc.x * o.x));
        // arg = -72.13*(|oc|^2 + |o|^2 - 2 oc.o) ; wr = 2^arg
        float arg = fmaf(144.26950408889634f, dot, fmaf(-72.13475204444817f, o.w, c0));
        bool p = msnz && (arg > SCREEN_T);
        unsigned m = __ballot_sync(0xffffffffu, p);
        if (m) {
            int leader = __ffs(m) - 1;
            unsigned bs = 0;
            if (lane == leader) bs = atomicAdd(cnt, (unsigned)__popc(m));
            bs = __shfl_sync(0xffffffffu, bs, leader);
            if (p) {
                unsigned slot = bs + (unsigned)__popc(m & lanemask);
                if (slot < CAP) lst[slot] = idbase + (unsigned)j;
            }
        }
    }
}

// Replay survivors exactly: sum wr * (|d0|^0.8+|d1|^0.8+|d2|^0.8).
__global__ void __launch_bounds__(256) small_kernel() {
    __shared__ float wpart[8];
    int t   = threadIdx.x;
    int reg = blockIdx.x >> 2;
    int sub = blockIdx.x & 3;
    unsigned n = g_cnt[reg * 32];
    if (n > CAP) n = CAP;
    const unsigned* lst = &g_list[reg * CAP];
    float acc = 0.f;
    for (unsigned k = (unsigned)(sub*256 + t); k < n; k += 1024u) {
        unsigned id = lst[k];
        unsigned offid = id & 2047u;
        int cidx = (int)(id >> 11);
        int yo = (int)(offid % KW) - WSZ;
        int xo = (int)(offid / KW) - WSZ;
        int c = cidx & (IW-1);
        int r = (cidx >> 7) & (IH-1);
        int b = cidx >> 14;
        int nidx = b*IH*IW + refl(r + xo, IH)*IW + refl(c + yo, IW);
        float4 oc = g_o4[cidx];
        float4 o  = g_o4[nidx];
        float4 sc = g_s4[cidx];
        float4 s  = g_s4[nidx];
        float u0 = oc.x - o.x, u1 = oc.y - o.y, u2 = oc.z - o.z;
        float rr = fmaf(u0, u0, fmaf(u1, u1, u2 * u2));
        float wr = ex2f(-72.13475204444817f * rr);
        float p0 = ex2f(0.8f * lg2f(fabsf(sc.x - s.x)));
        float p1 = ex2f(0.8f * lg2f(fabsf(sc.y - s.y)));
        float p2 = ex2f(0.8f * lg2f(fabsf(sc.z - s.z)));
        acc = fmaf(wr, p0 + p1 + p2, acc);    // m_small == 1 for survivors
    }
    #pragma unroll
    for (int off = 16; off; off >>= 1)
        acc += __shfl_xor_sync(0xffffffffu, acc, off);
    if ((t & 31) == 0) wpart[t >> 5] = acc;
    __syncthreads();
    if (t == 0) {
        float bs = 0.f;
        #pragma unroll
        for (int w = 0; w < 8; ++w) bs += wpart[w];
        atomicAdd(&g_partial[blockIdx.x & 255], (double)bs);
    }
}

__global__ void finalize_kernel(float* __restrict__ out) {
    __shared__ double sh[256];
    int t = threadIdx.x;
    sh[t] = g_partial[t];
    __syncthreads();
    for (int s = 128; s > 0; s >>= 1) {
        if (t < s) sh[t] += sh[t + s];
        __syncthreads();
    }
    if (t == 0) out[0] = (float)(sh[0] / (double)NPIX);
}

extern "C" void kernel_launch(void* const* d_in, const int* in_sizes, int n_in,
                              void* d_out, int out_size) {
    const float* orig = (const float*)d_in[0];
    const float* smo  = (const float*)d_in[1];
    float* out = (float*)d_out;
    (void)in_sizes; (void)n_in; (void)out_size;

    prep_kernel<<<256, 128>>>(orig, smo);
    conv_y_kernel<<<IB*IH, 128>>>();
    large_kernel<<<NPIX/256, 256>>>();
    screen_kernel<<<IB*IH*KW, 128>>>();     // 11008 blocks
    small_kernel<<<NREG*4, 256>>>();
    finalize_kernel<<<1, 256>>>(out);
}

// round 6
// speedup vs baseline: 1.9851x; 1.9851x over previous
#include <cuda_runtime.h>

#define WSZ 21
#define KW  43
#define IH  128
#define IW  128
#define IB  2
#define NPIX (IB*IH*IW)   // 32768
#define SCREEN_T (-26.0f)

// scratch (__device__ globals: no allocation allowed)
__device__ float4 g_s4[NPIX];    // smooth channels, .w = |s|^2
__device__ float4 g_o4[NPIX];    // orig channels,   .w = |o|^2
__device__ float  g_mask[NPIX];  // m_large
__device__ float4 g_tmp4[NPIX];  // conv scratch
__device__ float  g_swtab[KW+1]; // [KW] = total 2D spatial weight
__device__ double g_partial[256];

__device__ __forceinline__ float ex2f(float x) {
    float y;
    asm("ex2.approx.ftz.f32 %0, %1;" : "=f"(y) : "f"(x));
    return y;
}
__device__ __forceinline__ float lg2f(float x) {
    float y;
    asm("lg2.approx.ftz.f32 %0, %1;" : "=f"(y) : "f"(x));
    return y;
}

__device__ __forceinline__ int refl(int p, int n) {
    if (p < 0) p = -p;
    if (p >= n) p = 2*n - 2 - p;
    return p;
}

// Pack channels into float4 (+|.|^2 in .w), Sobel masks, spatial table.
__global__ void prep_kernel(const float* __restrict__ orig, const float* __restrict__ smo) {
    int idx = blockIdx.x * blockDim.x + threadIdx.x;
    if (idx < 256) g_partial[idx] = 0.0;
    if (idx < KW) {
        float d = (float)(idx - WSZ);
        g_swtab[idx] = expf(-(1.0f/98.0f) * d * d);   // SIGMA_SPACE = 1/(2*49)
    }
    if (idx == KW) {
        float s1 = 0.f;
        for (int x = -WSZ; x <= WSZ; ++x) s1 += expf(-(1.0f/98.0f) * (float)(x*x));
        g_swtab[KW] = s1 * s1;
    }
    if (idx >= NPIX) return;
    int c = idx & (IW-1);
    int r = (idx >> 7) & (IH-1);
    int b = idx >> 14;
    const float* ob = orig + b*3*IH*IW;
    const float* sb = smo  + b*3*IH*IW;
    int rm = refl(r-1, IH), rp = refl(r+1, IH);
    int cm = refl(c-1, IW), cp = refl(c+1, IW);
    float eo = 0.f, es = 0.f;
    float oo[3], ss[3];
    #pragma unroll
    for (int ch = 0; ch < 3; ++ch) {
        const float* p = ob + ch*IH*IW;
        float a00=p[rm*IW+cm], a01=p[rm*IW+c], a02=p[rm*IW+cp];
        float a10=p[r *IW+cm], a11=p[r *IW+c], a12=p[r *IW+cp];
        float a20=p[rp*IW+cm], a21=p[rp*IW+c], a22=p[rp*IW+cp];
        float gx = (a02 + 2.f*a12 + a22) - (a00 + 2.f*a10 + a20);
        float gy = (a20 + 2.f*a21 + a22) - (a00 + 2.f*a01 + a02);
        eo += sqrtf(gx*gx + gy*gy);
        oo[ch] = a11;
        const float* q = sb + ch*IH*IW;
        float b00=q[rm*IW+cm], b01=q[rm*IW+c], b02=q[rm*IW+cp];
        float b10=q[r *IW+cm], b11=q[r *IW+c], b12=q[r *IW+cp];
        float b20=q[rp*IW+cm], b21=q[rp*IW+c], b22=q[rp*IW+cp];
        float hx = (b02 + 2.f*b12 + b22) - (b00 + 2.f*b10 + b20);
        float hy = (b20 + 2.f*b21 + b22) - (b00 + 2.f*b01 + b02);
        es += sqrtf(hx*hx + hy*hy);
        ss[ch] = b11;
    }
    g_mask[idx] = ((eo < 20.f) && (es - eo > 10.f)) ? 1.f : 0.f;
    g_s4[idx] = make_float4(ss[0], ss[1], ss[2], ss[0]*ss[0]+ss[1]*ss[1]+ss[2]*ss[2]);
    g_o4[idx] = make_float4(oo[0], oo[1], oo[2], oo[0]*oo[0]+oo[1]*oo[1]+oo[2]*oo[2]);
}

// Pass 1 of separable Gaussian conv over (s.x,s.y,s.z,|s|^2): along columns.
__global__ void __launch_bounds__(128) conv_y_kernel() {
    __shared__ float4 row[IW + 2*WSZ];
    __shared__ float  wy[KW];
    int t  = threadIdx.x;
    int rg = blockIdx.x;          // 0..255 = batch*row
    int b  = rg >> 7;
    int r  = rg & (IH-1);
    int base = b*IH*IW + r*IW;
    for (int j = t; j < IW + 2*WSZ; j += 128)
        row[j] = g_s4[base + refl(j - WSZ, IW)];
    if (t < KW) wy[t] = g_swtab[t];
    __syncthreads();
    float4 a = make_float4(0.f, 0.f, 0.f, 0.f);
    #pragma unroll 4
    for (int j = 0; j < KW; ++j) {
        float  w = wy[j];
        float4 v = row[t + j];
        a.x = fmaf(w, v.x, a.x);
        a.y = fmaf(w, v.y, a.y);
        a.z = fmaf(w, v.z, a.z);
        a.w = fmaf(w, v.w, a.w);
    }
    g_tmp4[base + t] = a;
}

// Pass 2 (rows) + m_large term reduce (exact closed form):
//   large_i = mL_i * ( W*|s_i|^2 + (G*|s|^2)_i - 2 s_i . (G*s)_i )
__global__ void __launch_bounds__(256) large_kernel() {
    __shared__ float wpart[8];
    int t   = threadIdx.x;
    int idx = blockIdx.x * 256 + t;
    int c = idx & (IW-1);
    int r = (idx >> 7) & (IH-1);
    int b = idx >> 14;
    float4 a = make_float4(0.f, 0.f, 0.f, 0.f);
    #pragma unroll 4
    for (int j = 0; j < KW; ++j) {
        int rr = refl(r + j - WSZ, IH);
        float  w = g_swtab[j];
        float4 v = g_tmp4[b*IH*IW + rr*IW + c];
        a.x = fmaf(w, v.x, a.x);
        a.y = fmaf(w, v.y, a.y);
        a.z = fmaf(w, v.z, a.z);
        a.w = fmaf(w, v.w, a.w);
    }
    float4 s  = g_s4[idx];
    float Wsum = g_swtab[KW];
    float dot = s.x*a.x + s.y*a.y + s.z*a.z;
    float val = g_mask[idx] * (fmaf(Wsum, s.w, a.w) - 2.f*dot);
    #pragma unroll
    for (int off = 16; off; off >>= 1)
        val += __shfl_xor_sync(0xffffffffu, val, off);
    if ((t & 31) == 0) wpart[t >> 5] = val;
    __syncthreads();
    if (t == 0) {
        float bs = 0.f;
        #pragma unroll
        for (int w = 0; w < 8; ++w) bs += wpart[w];
        atomicAdd(&g_partial[blockIdx.x & 255], (double)bs);
    }
}

// Fused screen + replay for the m_small term.
// Screen loop: only o4 reads (16B/unit), register bitmask of survivors.
// Replay: per-thread, exact fp32/MUFU math on ~2% of units.
__global__ void __launch_bounds__(128) main_kernel() {
    __shared__ float4 sO[IW + 2*WSZ];   // 170
    __shared__ float4 sS[IW + 2*WSZ];
    __shared__ float  wpart[4];

    int t  = threadIdx.x;
    int bx = blockIdx.x;
    int xob = bx % KW;           // 0..42
    int rg = bx / KW;            // 0..255
    int b  = rg >> 7;
    int r  = rg & (IH-1);

    int srow = refl(r + xob - WSZ, IH);
    int base = b*IH*IW + srow*IW;
    for (int j = t; j < IW + 2*WSZ; j += 128) {
        int cj = refl(j - WSZ, IW);
        sO[j] = g_o4[base + cj];
        sS[j] = g_s4[base + cj];
    }
    __syncthreads();

    int cidx = b*IH*IW + r*IW + t;
    float4 oc = g_o4[cidx];
    bool msnz = (g_mask[cidx] == 0.f);     // m_small != 0
    float c0 = -72.13475204444817f * oc.w;
    float c0s = msnz ? c0 : -3.0e38f;      // kill all survivors if m_small == 0

    unsigned mlo = 0u, mhi = 0u;
    #pragma unroll
    for (int j = 0; j < KW; ++j) {
        float4 o = sO[t + j];
        float dot = fmaf(oc.z, o.z, fmaf(oc.y, o.y, oc.x * o.x));
        // arg(log2) = -72.13*(|oc|^2 + |o|^2 - 2 oc.o)
        float arg = fmaf(144.26950408889634f, dot, fmaf(-72.13475204444817f, o.w, c0s));
        if (j < 32) { if (arg > SCREEN_T) mlo |= (1u << j); }
        else        { if (arg > SCREEN_T) mhi |= (1u << (j - 32)); }
    }

    float acc = 0.f;
    float4 sc = sS[t + WSZ];   // == g_s4[cidx] (center column in this padded row only when xob==WSZ)
    sc = g_s4[cidx];           // load center smooth exactly
    while (mlo) {
        int j = __ffs(mlo) - 1; mlo &= mlo - 1;
        float4 o = sO[t + j];
        float4 s = sS[t + j];
        float dot = fmaf(oc.z, o.z, fmaf(oc.y, o.y, oc.x * o.x));
        float arg = fmaf(144.26950408889634f, dot, fmaf(-72.13475204444817f, o.w, c0));
        float wr = ex2f(arg);
        float p0 = ex2f(0.8f * lg2f(fabsf(sc.x - s.x)));
        float p1 = ex2f(0.8f * lg2f(fabsf(sc.y - s.y)));
        float p2 = ex2f(0.8f * lg2f(fabsf(sc.z - s.z)));
        acc = fmaf(wr, p0 + p1 + p2, acc);
    }
    while (mhi) {
        int j = __ffs(mhi) - 1 + 32; mhi &= mhi - 1;
        float4 o = sO[t + j];
        float4 s = sS[t + j];
        float dot = fmaf(oc.z, o.z, fmaf(oc.y, o.y, oc.x * o.x));
        float arg = fmaf(144.26950408889634f, dot, fmaf(-72.13475204444817f, o.w, c0));
        float wr = ex2f(arg);
        float p0 = ex2f(0.8f * lg2f(fabsf(sc.x - s.x)));
        float p1 = ex2f(0.8f * lg2f(fabsf(sc.y - s.y)));
        float p2 = ex2f(0.8f * lg2f(fabsf(sc.z - s.z)));
        acc = fmaf(wr, p0 + p1 + p2, acc);
    }

    // warp reduce
    #pragma unroll
    for (int off = 16; off; off >>= 1)
        acc += __shfl_xor_sync(0xffffffffu, acc, off);
    if ((t & 31) == 0) wpart[t >> 5] = acc;
    __syncthreads();
    if (t == 0) {
        float bs = wpart[0] + wpart[1] + wpart[2] + wpart[3];
        atomicAdd(&g_partial[bx & 255], (double)bs);
    }
}

__global__ void finalize_kernel(float* __restrict__ out) {
    __shared__ double sh[256];
    int t = threadIdx.x;
    sh[t] = g_partial[t];
    __syncthreads();
    for (int s = 128; s > 0; s >>= 1) {
        if (t < s) sh[t] += sh[t + s];
        __syncthreads();
    }
    if (t == 0) out[0] = (float)(sh[0] / (double)NPIX);
}

extern "C" void kernel_launch(void* const* d_in, const int* in_sizes, int n_in,
                              void* d_out, int out_size) {
    const float* orig = (const float*)d_in[0];
    const float* smo  = (const float*)d_in[1];
    float* out = (float*)d_out;
    (void)in_sizes; (void)n_in; (void)out_size;

    prep_kernel<<<256, 128>>>(orig, smo);
    conv_y_kernel<<<IB*IH, 128>>>();
    large_kernel<<<NPIX/256, 256>>>();
    main_kernel<<<IB*IH*KW, 128>>>();       // 11008 blocks
    finalize_kernel<<<1, 256>>>(out);
}

// round 7
// speedup vs baseline: 2.3442x; 1.1809x over previous
#include <cuda_runtime.h>
#include <cuda_fp16.h>

#define WSZ 21
#define KW  43
#define IH  128
#define IW  128
#define IB  2
#define NPIX (IB*IH*IW)   // 32768

// scratch (__device__ globals: no allocation allowed)
__device__ float4 g_s4[NPIX];    // smooth channels, .w = |s|^2
__device__ float4 g_o4[NPIX];    // orig channels,   .w = |o|^2
__device__ uint2  g_oh[NPIX];    // fp16 pack: (o.x,o.y) , (o.z, -|o|^2/2)
__device__ float  g_mask[NPIX];  // m_large
__device__ float4 g_tmp4[NPIX];  // conv scratch
__device__ float  g_swtab[KW+1]; // [KW] = total 2D spatial weight
__device__ double g_partial[256];

__device__ __forceinline__ float ex2f(float x) {
    float y;
    asm("ex2.approx.ftz.f32 %0, %1;" : "=f"(y) : "f"(x));
    return y;
}
__device__ __forceinline__ float lg2f(float x) {
    float y;
    asm("lg2.approx.ftz.f32 %0, %1;" : "=f"(y) : "f"(x));
    return y;
}

__device__ __forceinline__ int refl(int p, int n) {
    if (p < 0) p = -p;
    if (p >= n) p = 2*n - 2 - p;
    return p;
}

__device__ __forceinline__ unsigned h2u(__half2 h) {
    unsigned u; 
    asm("mov.b32 %0, %1;" : "=r"(u) : "r"(*(unsigned*)&h));
    return u;
}

// Pack channels, fp16 screen pack, Sobel masks, spatial table.
__global__ void prep_kernel(const float* __restrict__ orig, const float* __restrict__ smo) {
    int idx = blockIdx.x * blockDim.x + threadIdx.x;
    if (idx < 256) g_partial[idx] = 0.0;
    if (idx < KW) {
        float d = (float)(idx - WSZ);
        g_swtab[idx] = expf(-(1.0f/98.0f) * d * d);   // SIGMA_SPACE = 1/(2*49)
    }
    if (idx == KW) {
        float s1 = 0.f;
        for (int x = -WSZ; x <= WSZ; ++x) s1 += expf(-(1.0f/98.0f) * (float)(x*x));
        g_swtab[KW] = s1 * s1;
    }
    if (idx >= NPIX) return;
    int c = idx & (IW-1);
    int r = (idx >> 7) & (IH-1);
    int b = idx >> 14;
    const float* ob = orig + b*3*IH*IW;
    const float* sb = smo  + b*3*IH*IW;
    int rm = refl(r-1, IH), rp = refl(r+1, IH);
    int cm = refl(c-1, IW), cp = refl(c+1, IW);
    float eo = 0.f, es = 0.f;
    float oo[3], ss[3];
    #pragma unroll
    for (int ch = 0; ch < 3; ++ch) {
        const float* p = ob + ch*IH*IW;
        float a00=p[rm*IW+cm], a01=p[rm*IW+c], a02=p[rm*IW+cp];
        float a10=p[r *IW+cm], a11=p[r *IW+c], a12=p[r *IW+cp];
        float a20=p[rp*IW+cm], a21=p[rp*IW+c], a22=p[rp*IW+cp];
        float gx = (a02 + 2.f*a12 + a22) - (a00 + 2.f*a10 + a20);
        float gy = (a20 + 2.f*a21 + a22) - (a00 + 2.f*a01 + a02);
        eo += sqrtf(gx*gx + gy*gy);
        oo[ch] = a11;
        const float* q = sb + ch*IH*IW;
        float b00=q[rm*IW+cm], b01=q[rm*IW+c], b02=q[rm*IW+cp];
        float b10=q[r *IW+cm], b11=q[r *IW+c], b12=q[r *IW+cp];
        float b20=q[rp*IW+cm], b21=q[rp*IW+c], b22=q[rp*IW+cp];
        float hx = (b02 + 2.f*b12 + b22) - (b00 + 2.f*b10 + b20);
        float hy = (b20 + 2.f*b21 + b22) - (b00 + 2.f*b01 + b02);
        es += sqrtf(hx*hx + hy*hy);
        ss[ch] = b11;
    }
    g_mask[idx] = ((eo < 20.f) && (es - eo > 10.f)) ? 1.f : 0.f;
    float sw = ss[0]*ss[0]+ss[1]*ss[1]+ss[2]*ss[2];
    float ow = oo[0]*oo[0]+oo[1]*oo[1]+oo[2]*oo[2];
    g_s4[idx] = make_float4(ss[0], ss[1], ss[2], sw);
    g_o4[idx] = make_float4(oo[0], oo[1], oo[2], ow);
    __half2 ha = __floats2half2_rn(oo[0], oo[1]);
    __half2 hb = __floats2half2_rn(oo[2], -0.5f*ow);
    g_oh[idx] = make_uint2(h2u(ha), h2u(hb));
}

// Pass 1 of separable Gaussian conv over (s.x,s.y,s.z,|s|^2): along columns.
__global__ void __launch_bounds__(128) conv_y_kernel() {
    __shared__ float4 row[IW + 2*WSZ];
    __shared__ float  wy[KW];
    int t  = threadIdx.x;
    int rg = blockIdx.x;          // 0..255 = batch*row
    int b  = rg >> 7;
    int r  = rg & (IH-1);
    int base = b*IH*IW + r*IW;
    for (int j = t; j < IW + 2*WSZ; j += 128)
        row[j] = g_s4[base + refl(j - WSZ, IW)];
    if (t < KW) wy[t] = g_swtab[t];
    __syncthreads();
    float4 a = make_float4(0.f, 0.f, 0.f, 0.f);
    #pragma unroll 4
    for (int j = 0; j < KW; ++j) {
        float  w = wy[j];
        float4 v = row[t + j];
        a.x = fmaf(w, v.x, a.x);
        a.y = fmaf(w, v.y, a.y);
        a.z = fmaf(w, v.z, a.z);
        a.w = fmaf(w, v.w, a.w);
    }
    g_tmp4[base + t] = a;
}

// Pass 2 (rows) + m_large term reduce (exact closed form):
//   large_i = mL_i * ( W*|s_i|^2 + (G*|s|^2)_i - 2 s_i . (G*s)_i )
__global__ void __launch_bounds__(256) large_kernel() {
    __shared__ float wpart[8];
    int t   = threadIdx.x;
    int idx = blockIdx.x * 256 + t;
    int c = idx & (IW-1);
    int r = (idx >> 7) & (IH-1);
    int b = idx >> 14;
    float4 a = make_float4(0.f, 0.f, 0.f, 0.f);
    #pragma unroll 4
    for (int j = 0; j < KW; ++j) {
        int rr = refl(r + j - WSZ, IH);
        float  w = g_swtab[j];
        float4 v = g_tmp4[b*IH*IW + rr*IW + c];
        a.x = fmaf(w, v.x, a.x);
        a.y = fmaf(w, v.y, a.y);
        a.z = fmaf(w, v.z, a.z);
        a.w = fmaf(w, v.w, a.w);
    }
    float4 s  = g_s4[idx];
    float Wsum = g_swtab[KW];
    float dot = s.x*a.x + s.y*a.y + s.z*a.z;
    float val = g_mask[idx] * (fmaf(Wsum, s.w, a.w) - 2.f*dot);
    #pragma unroll
    for (int off = 16; off; off >>= 1)
        val += __shfl_xor_sync(0xffffffffu, val, off);
    if ((t & 31) == 0) wpart[t >> 5] = val;
    __syncthreads();
    if (t == 0) {
        float bs = 0.f;
        #pragma unroll
        for (int w = 0; w < 8; ++w) bs += wpart[w];
        atomicAdd(&g_partial[blockIdx.x & 255], (double)bs);
    }
}

// Fused fp16 screen + exact fp32 replay for the m_small term.
__global__ void __launch_bounds__(128) main_kernel() {
    __shared__ alignas(8) uint2  sH[IW + 2*WSZ];   // fp16 screen pack (8B)
    __shared__ float4 sO[IW + 2*WSZ];              // exact orig (replay only)
    __shared__ float4 sS[IW + 2*WSZ];              // exact smooth (replay only)
    __shared__ float  wpart[4];

    int t  = threadIdx.x;
    int bx = blockIdx.x;
    int xob = bx % KW;           // 0..42
    int rg = bx / KW;            // 0..255
    int b  = rg >> 7;
    int r  = rg & (IH-1);

    int srow = refl(r + xob - WSZ, IH);
    int base = b*IH*IW + srow*IW;
    for (int j = t; j < IW + 2*WSZ; j += 128) {
        int cj = refl(j - WSZ, IW);
        sH[j] = g_oh[base + cj];
        sO[j] = g_o4[base + cj];
        sS[j] = g_s4[base + cj];
    }
    __syncthreads();

    int cidx = b*IH*IW + r*IW + t;
    float4 oc = g_o4[cidx];
    bool msnz = (g_mask[cidx] == 0.f);     // m_small != 0
    // survivor: dot(oc,o) - |o|^2/2 > 0.5*|oc|^2 - 26/144.27 - margin
    float thr_f = msnz ? (0.5f*oc.w - 0.18022f - 0.06f) : 3.0e38f;
    __half  thr_h = __float2half_rn(thr_f);
    __half2 ca = __floats2half2_rn(oc.x, oc.y);
    __half2 cb = __floats2half2_rn(oc.z, 1.0f);

    unsigned mlo = 0u, mhi = 0u;
    #pragma unroll
    for (int j = 0; j < KW; ++j) {
        uint2 u = sH[t + j];
        __half2 a = *(__half2*)&u.x;
        __half2 bb = *(__half2*)&u.y;
        __half2 v2 = __hfma2(cb, bb, __hmul2(ca, a));
        __half2 s2 = __hadd2(v2, __lowhigh2highlow(v2));   // both lanes = lo+hi
        bool p = __hgt(__low2half(s2), thr_h);
        if (j < 32) { if (p) mlo |= (1u << j); }
        else        { if (p) mhi |= (1u << (j - 32)); }
    }

    float c0 = -72.13475204444817f * oc.w;
    float4 sc = g_s4[cidx];
    float acc = 0.f;
    while (mlo) {
        int j = __ffs(mlo) - 1; mlo &= mlo - 1;
        float4 o = sO[t + j];
        float4 s = sS[t + j];
        float dot = fmaf(oc.z, o.z, fmaf(oc.y, o.y, oc.x * o.x));
        float arg = fmaf(144.26950408889634f, dot, fmaf(-72.13475204444817f, o.w, c0));
        float wr = ex2f(arg);
        float p0 = ex2f(0.8f * lg2f(fabsf(sc.x - s.x)));
        float p1 = ex2f(0.8f * lg2f(fabsf(sc.y - s.y)));
        float p2 = ex2f(0.8f * lg2f(fabsf(sc.z - s.z)));
        acc = fmaf(wr, p0 + p1 + p2, acc);
    }
    while (mhi) {
        int j = __ffs(mhi) - 1 + 32; mhi &= mhi - 1;
        float4 o = sO[t + j];
        float4 s = sS[t + j];
        float dot = fmaf(oc.z, o.z, fmaf(oc.y, o.y, oc.x * o.x));
        float arg = fmaf(144.26950408889634f, dot, fmaf(-72.13475204444817f, o.w, c0));
        float wr = ex2f(arg);
        float p0 = ex2f(0.8f * lg2f(fabsf(sc.x - s.x)));
        float p1 = ex2f(0.8f * lg2f(fabsf(sc.y - s.y)));
        float p2 = ex2f(0.8f * lg2f(fabsf(sc.z - s.z)));
        acc = fmaf(wr, p0 + p1 + p2, acc);
    }

    // warp reduce
    #pragma unroll
    for (int off = 16; off; off >>= 1)
        acc += __shfl_xor_sync(0xffffffffu, acc, off);
    if ((t & 31) == 0) wpart[t >> 5] = acc;
    __syncthreads();
    if (t == 0) {
        float bs = wpart[0] + wpart[1] + wpart[2] + wpart[3];
        atomicAdd(&g_partial[bx & 255], (double)bs);
    }
}

__global__ void finalize_kernel(float* __restrict__ out) {
    __shared__ double sh[256];
    int t = threadIdx.x;
    sh[t] = g_partial[t];
    __syncthreads();
    for (int s = 128; s > 0; s >>= 1) {
        if (t < s) sh[t] += sh[t + s];
        __syncthreads();
    }
    if (t == 0) out[0] = (float)(sh[0] / (double)NPIX);
}

extern "C" void kernel_launch(void* const* d_in, const int* in_sizes, int n_in,
                              void* d_out, int out_size) {
    const float* orig = (const float*)d_in[0];
    const float* smo  = (const float*)d_in[1];
    float* out = (float*)d_out;
    (void)in_sizes; (void)n_in; (void)out_size;

    prep_kernel<<<256, 128>>>(orig, smo);
    conv_y_kernel<<<IB*IH, 128>>>();
    large_kernel<<<NPIX/256, 256>>>();
    main_kernel<<<IB*IH*KW, 128>>>();       // 11008 blocks
    finalize_kernel<<<1, 256>>>(out);
}